// round 1
// baseline (speedup 1.0000x reference)
#include <cuda_runtime.h>
#include <math.h>

// ---------------------------------------------------------------------------
// Problem constants
// ---------------------------------------------------------------------------
constexpr int B_    = 16;
constexpr int C_    = 256;
constexpr int L_    = 2048;
constexpr int ZD_   = 128;
constexpr int TEMB_ = 512;
constexpr size_t BCL = (size_t)B_ * C_ * L_;

// ---------------------------------------------------------------------------
// Scratch (device globals; allocation-free per harness rules)
// ---------------------------------------------------------------------------
__device__ float g_t1 [BCL];                    // silu(norm(...)) staging
__device__ float g_h  [BCL];                    // after conv1 + add
__device__ float g_x1 [BCL];                    // x + conv2(...)
__device__ float g_hn [BCL];                    // chan_norm(x1)
__device__ float g_q  [BCL];
__device__ float g_k  [BCL];
__device__ float g_v  [BCL];
__device__ float g_h2 [BCL];                    // attention output (pre-proj)
__device__ float g_w  [(size_t)B_ * L_ * L_];   // [B, L, L] attention scores
__device__ float g_add[B_ * C_];                // temb/z projection vector

static __device__ __forceinline__ float silu_f(float x) {
    return x / (1.f + expf(-x));
}

// ---------------------------------------------------------------------------
// Kernel 1: timestep embedding MLP + fused add-vector
//   add[b,c] = silu(temb)@tpw + tpb + (silu(z0)+silu(zt))@zpw + 2*zpb
// One block per batch, 512 threads. Tiny cost.
// ---------------------------------------------------------------------------
__global__ void temb_kernel(const int* __restrict__ t,
                            const float* __restrict__ z0,
                            const float* __restrict__ zt,
                            const float* __restrict__ tw1, const float* __restrict__ tb1,
                            const float* __restrict__ tw2, const float* __restrict__ tb2,
                            const float* __restrict__ tpw, const float* __restrict__ tpb,
                            const float* __restrict__ zpw, const float* __restrict__ zpb)
{
    __shared__ float se[128];   // timestep embedding
    __shared__ float s1[512];   // silu(emb @ tw1 + tb1)
    __shared__ float s2[512];   // silu(temb)
    __shared__ float sz[256];   // silu(z0) | silu(zt)

    int b = blockIdx.x, tid = threadIdx.x;

    if (tid < 64) {
        float f = expf((float)tid * (-logf(10000.f) / 63.f));
        float a = (float)t[b] * f;
        se[tid]      = sinf(a);
        se[64 + tid] = cosf(a);
    }
    if (tid < 128) {
        sz[tid]       = silu_f(z0[b * ZD_ + tid]);
        sz[128 + tid] = silu_f(zt[b * ZD_ + tid]);
    }
    __syncthreads();

    {   // layer 1: 128 -> 512, silu
        float acc = tb1[tid];
        #pragma unroll 8
        for (int i = 0; i < 128; i++) acc += se[i] * tw1[i * TEMB_ + tid];
        s1[tid] = silu_f(acc);
    }
    __syncthreads();
    {   // layer 2: 512 -> 512, then silu (we only ever need silu(temb))
        float acc = tb2[tid];
        #pragma unroll 8
        for (int k = 0; k < 512; k++) acc += s1[k] * tw2[k * TEMB_ + tid];
        s2[tid] = silu_f(acc);
    }
    __syncthreads();

    if (tid < C_) {
        float acc = tpb[tid] + 2.f * zpb[tid];
        #pragma unroll 8
        for (int j = 0; j < 512; j++) acc += s2[j] * tpw[j * C_ + tid];
        #pragma unroll 8
        for (int i = 0; i < 128; i++) acc += (sz[i] + sz[128 + i]) * zpw[i * C_ + tid];
        g_add[b * C_ + tid] = acc;
    }
}

// ---------------------------------------------------------------------------
// Kernel 2: per-(b,c) channel norm over L (GroupNorm groups==channels),
// optional fused silu. One block (256 thr) per row; 8 elems/thread in regs.
// ---------------------------------------------------------------------------
__global__ __launch_bounds__(256) void norm_kernel(const float* __restrict__ in,
                                                   float* __restrict__ out,
                                                   const float* __restrict__ gam,
                                                   const float* __restrict__ bet,
                                                   int doSilu)
{
    __shared__ float red[64];
    int row = blockIdx.x, tid = threadIdx.x;
    const float* p = in + (size_t)row * L_;

    float v[8];
    float s = 0.f, sq = 0.f;
    #pragma unroll
    for (int i = 0; i < 8; i++) {
        v[i] = p[tid + i * 256];
        s  += v[i];
        sq += v[i] * v[i];
    }
    #pragma unroll
    for (int o = 16; o > 0; o >>= 1) {
        s  += __shfl_down_sync(0xffffffffu, s,  o);
        sq += __shfl_down_sync(0xffffffffu, sq, o);
    }
    if ((tid & 31) == 0) { red[tid >> 5] = s; red[8 + (tid >> 5)] = sq; }
    __syncthreads();
    if (tid < 32) {
        float a  = (tid < 8) ? red[tid]     : 0.f;
        float b2 = (tid < 8) ? red[8 + tid] : 0.f;
        #pragma unroll
        for (int o = 4; o > 0; o >>= 1) {
            a  += __shfl_down_sync(0xffffffffu, a,  o);
            b2 += __shfl_down_sync(0xffffffffu, b2, o);
        }
        if (tid == 0) { red[32] = a; red[33] = b2; }
    }
    __syncthreads();

    float mean = red[32] * (1.f / L_);
    float var  = red[33] * (1.f / L_) - mean * mean;
    float rstd = rsqrtf(var + 1e-6f);
    int c = row & (C_ - 1);
    float gm = gam[c], bt = bet[c];

    float* q = out + (size_t)row * L_;
    #pragma unroll
    for (int i = 0; i < 8; i++) {
        float y = (v[i] - mean) * rstd * gm + bt;
        if (doSilu) y = y / (1.f + expf(-y));
        q[tid + i * 256] = y;
    }
}

// ---------------------------------------------------------------------------
// Kernel 3: 3-tap conv over channels (implicit GEMM), pad=1.
//   out[b,o,l] = sum_{i,k} w[o,i,k] * in[b,i,l+k-1] + bias[o]
//                (+ add[b,o])  (+ resid[b,o,l])
// Block tile: 32 o x 128 l, ci chunks of 32. 256 threads; 4o x 4l per thread.
// ---------------------------------------------------------------------------
constexpr int CONV_OT = 32;
constexpr int CONV_LT = 128;
constexpr int CONV_CI = 32;

__global__ __launch_bounds__(256) void conv3_kernel(const float* __restrict__ in,
                                                    const float* __restrict__ w,
                                                    const float* __restrict__ bias,
                                                    const float* __restrict__ addv,
                                                    const float* __restrict__ resid,
                                                    float* __restrict__ out)
{
    __shared__ float sIn[CONV_CI][132];             // [32][130 used, pad to 132]
    __shared__ float sW[CONV_OT * CONV_CI * 3];     // [o][c][k]

    int b  = blockIdx.z;
    int o0 = blockIdx.y * CONV_OT;
    int l0 = blockIdx.x * CONV_LT;
    int tid = threadIdx.x;
    int tx = tid & 31, ty = tid >> 5;               // tx: l-group, ty: o-lane

    float acc[4][4] = {};

    for (int ci = 0; ci < C_; ci += CONV_CI) {
        __syncthreads();
        // stage input patch [32][130] (zero-padded at sequence edges)
        for (int idx = tid; idx < CONV_CI * 132; idx += 256) {
            int c = idx / 132, p = idx % 132;
            int gl = l0 - 1 + p;
            float val = 0.f;
            if (p < 130 && gl >= 0 && gl < L_)
                val = in[((size_t)(b * C_ + ci + c)) * L_ + gl];
            sIn[c][p] = val;
        }
        // stage weights [32 o][32 c][3 k]
        for (int idx = tid; idx < CONV_OT * CONV_CI * 3; idx += 256) {
            int o = idx / (CONV_CI * 3), r = idx % (CONV_CI * 3);
            int c = r / 3, k = r % 3;
            sW[idx] = w[(size_t)(o0 + o) * (C_ * 3) + (ci + c) * 3 + k];
        }
        __syncthreads();

        #pragma unroll 4
        for (int c = 0; c < CONV_CI; c++) {
            float4 i4 = *(const float4*)&sIn[c][4 * tx];
            float i5 = sIn[c][4 * tx + 4];
            float i6 = sIn[c][4 * tx + 5];
            float inv[6] = { i4.x, i4.y, i4.z, i4.w, i5, i6 };
            #pragma unroll
            for (int jj = 0; jj < 4; jj++) {
                const float* wp = &sW[(ty + 8 * jj) * (CONV_CI * 3) + c * 3];
                float w0 = wp[0], w1 = wp[1], w2 = wp[2];
                #pragma unroll
                for (int j = 0; j < 4; j++)
                    acc[jj][j] += w0 * inv[j] + w1 * inv[j + 1] + w2 * inv[j + 2];
            }
        }
    }

    #pragma unroll
    for (int jj = 0; jj < 4; jj++) {
        int o = o0 + ty + 8 * jj;
        float base = bias[o];
        if (addv) base += addv[b * C_ + o];
        size_t rowoff = ((size_t)(b * C_ + o)) * L_ + l0 + 4 * tx;
        #pragma unroll
        for (int j = 0; j < 4; j++) {
            float val = acc[jj][j] + base;
            if (resid) val += resid[rowoff + j];
            out[rowoff + j] = val;
        }
    }
}

// ---------------------------------------------------------------------------
// Kernel 4: templated 128x128x8 SGEMM, 256 threads, 8x8 per thread.
//   C[m,n] = alpha * sum_k A(k,m)*B(k,n)  (+ bias[m]) (+ res[m,n])
// Layout 0: X(k,i) = X[k*ld + i]   (k-major, i contiguous)
// Layout 1: X(k,i) = X[i*ld + k]   (i-major, k contiguous)
// ---------------------------------------------------------------------------
template <int LAYA, int LAYB, bool BIAS, bool RES>
__global__ __launch_bounds__(256) void gemm128(const float* __restrict__ A,
                                               const float* __restrict__ Bm,
                                               const float* __restrict__ bias,
                                               const float* __restrict__ res,
                                               float* __restrict__ Cm,
                                               int M, int N, int K,
                                               int lda, int ldb, float alpha,
                                               size_t strideA, size_t strideB, size_t strideC)
{
    __shared__ float sA[8][128];
    __shared__ float sB[8][128];

    int bz = blockIdx.z;
    A  += strideA * bz;
    Bm += strideB * bz;
    float* Cp = Cm + strideC * bz;

    int m0 = blockIdx.y * 128, n0 = blockIdx.x * 128;
    int tid = threadIdx.x;
    int tm = tid >> 4, tn = tid & 15;

    float acc[8][8] = {};

    for (int k0 = 0; k0 < K; k0 += 8) {
        __syncthreads();
        if (LAYA == 0) {
            int kk = tid >> 5, m = (tid & 31) * 4;
            *(float4*)&sA[kk][m] = *(const float4*)&A[(size_t)(k0 + kk) * lda + m0 + m];
        } else {
            int m = tid >> 1, kk = (tid & 1) * 4;
            float4 v4 = *(const float4*)&A[(size_t)(m0 + m) * lda + k0 + kk];
            sA[kk + 0][m] = v4.x; sA[kk + 1][m] = v4.y;
            sA[kk + 2][m] = v4.z; sA[kk + 3][m] = v4.w;
        }
        if (LAYB == 0) {
            int kk = tid >> 5, n = (tid & 31) * 4;
            *(float4*)&sB[kk][n] = *(const float4*)&Bm[(size_t)(k0 + kk) * ldb + n0 + n];
        } else {
            int n = tid >> 1, kk = (tid & 1) * 4;
            float4 v4 = *(const float4*)&Bm[(size_t)(n0 + n) * ldb + k0 + kk];
            sB[kk + 0][n] = v4.x; sB[kk + 1][n] = v4.y;
            sB[kk + 2][n] = v4.z; sB[kk + 3][n] = v4.w;
        }
        __syncthreads();

        #pragma unroll
        for (int kk = 0; kk < 8; kk++) {
            float a[8], bv[8];
            *(float4*)&a[0]  = *(const float4*)&sA[kk][tm * 4];
            *(float4*)&a[4]  = *(const float4*)&sA[kk][tm * 4 + 64];
            *(float4*)&bv[0] = *(const float4*)&sB[kk][tn * 4];
            *(float4*)&bv[4] = *(const float4*)&sB[kk][tn * 4 + 64];
            #pragma unroll
            for (int i = 0; i < 8; i++)
                #pragma unroll
                for (int j = 0; j < 8; j++)
                    acc[i][j] += a[i] * bv[j];
        }
    }

    #pragma unroll
    for (int mi = 0; mi < 2; mi++) {
        #pragma unroll
        for (int i = 0; i < 4; i++) {
            int m = m0 + tm * 4 + mi * 64 + i;
            float bvv = BIAS ? bias[m] : 0.f;
            size_t rowoff = (size_t)m * N;
            #pragma unroll
            for (int ni = 0; ni < 2; ni++) {
                int n = n0 + tn * 4 + ni * 64;
                float4 o4;
                o4.x = acc[mi * 4 + i][ni * 4 + 0] * alpha + bvv;
                o4.y = acc[mi * 4 + i][ni * 4 + 1] * alpha + bvv;
                o4.z = acc[mi * 4 + i][ni * 4 + 2] * alpha + bvv;
                o4.w = acc[mi * 4 + i][ni * 4 + 3] * alpha + bvv;
                if (RES) {
                    float4 r4 = *(const float4*)&res[strideC * bz + rowoff + n];
                    o4.x += r4.x; o4.y += r4.y; o4.z += r4.z; o4.w += r4.w;
                }
                *(float4*)&Cp[rowoff + n] = o4;
            }
        }
    }
}

// ---------------------------------------------------------------------------
// Kernel 5: row softmax over j (length L). One block (256 thr) per (b,i) row.
// ---------------------------------------------------------------------------
__global__ __launch_bounds__(256) void softmax_kernel(float* __restrict__ w)
{
    __shared__ float red[8];
    __shared__ float red2[8];
    size_t row = blockIdx.x;
    float* p = w + row * (size_t)L_;
    int tid = threadIdx.x;

    float v[8];
    float mx = -1e30f;
    #pragma unroll
    for (int i = 0; i < 8; i++) { v[i] = p[tid + i * 256]; mx = fmaxf(mx, v[i]); }
    #pragma unroll
    for (int o = 16; o > 0; o >>= 1) mx = fmaxf(mx, __shfl_xor_sync(0xffffffffu, mx, o));
    if ((tid & 31) == 0) red[tid >> 5] = mx;
    __syncthreads();
    float m = red[0];
    #pragma unroll
    for (int i = 1; i < 8; i++) m = fmaxf(m, red[i]);

    float s = 0.f;
    #pragma unroll
    for (int i = 0; i < 8; i++) { v[i] = expf(v[i] - m); s += v[i]; }
    #pragma unroll
    for (int o = 16; o > 0; o >>= 1) s += __shfl_xor_sync(0xffffffffu, s, o);
    if ((tid & 31) == 0) red2[tid >> 5] = s;
    __syncthreads();
    float tot = 0.f;
    #pragma unroll
    for (int i = 0; i < 8; i++) tot += red2[i];
    float inv = 1.f / tot;
    #pragma unroll
    for (int i = 0; i < 8; i++) p[tid + i * 256] = v[i] * inv;
}

// ---------------------------------------------------------------------------
// Host orchestration (graph-capturable: kernel launches only)
// ---------------------------------------------------------------------------
extern "C" void kernel_launch(void* const* d_in, const int* in_sizes, int n_in,
                              void* d_out, int out_size)
{
    (void)in_sizes; (void)n_in; (void)out_size;

    const float* x   = (const float*)d_in[0];
    const int*   t   = (const int*)  d_in[1];
    const float* z0  = (const float*)d_in[2];
    const float* zt  = (const float*)d_in[3];
    const float* tw1 = (const float*)d_in[4];
    const float* tb1 = (const float*)d_in[5];
    const float* tw2 = (const float*)d_in[6];
    const float* tb2 = (const float*)d_in[7];
    const float* tpw = (const float*)d_in[8];
    const float* tpb = (const float*)d_in[9];
    const float* zpw = (const float*)d_in[10];
    const float* zpb = (const float*)d_in[11];
    const float* n1g = (const float*)d_in[12];
    const float* n1b = (const float*)d_in[13];
    const float* n2g = (const float*)d_in[14];
    const float* n2b = (const float*)d_in[15];
    const float* ng  = (const float*)d_in[16];
    const float* nb  = (const float*)d_in[17];
    const float* c1w = (const float*)d_in[18];
    const float* c1b = (const float*)d_in[19];
    const float* c2w = (const float*)d_in[20];
    const float* c2b = (const float*)d_in[21];
    const float* qw  = (const float*)d_in[22];
    const float* qb  = (const float*)d_in[23];
    const float* kw  = (const float*)d_in[24];
    const float* kb  = (const float*)d_in[25];
    const float* vw  = (const float*)d_in[26];
    const float* vb  = (const float*)d_in[27];
    const float* pw  = (const float*)d_in[28];
    const float* pb  = (const float*)d_in[29];
    float* out = (float*)d_out;

    float *p_t1, *p_h, *p_x1, *p_hn, *p_q, *p_k, *p_v, *p_h2, *p_w, *p_add;
    cudaGetSymbolAddress((void**)&p_t1,  g_t1);
    cudaGetSymbolAddress((void**)&p_h,   g_h);
    cudaGetSymbolAddress((void**)&p_x1,  g_x1);
    cudaGetSymbolAddress((void**)&p_hn,  g_hn);
    cudaGetSymbolAddress((void**)&p_q,   g_q);
    cudaGetSymbolAddress((void**)&p_k,   g_k);
    cudaGetSymbolAddress((void**)&p_v,   g_v);
    cudaGetSymbolAddress((void**)&p_h2,  g_h2);
    cudaGetSymbolAddress((void**)&p_w,   g_w);
    cudaGetSymbolAddress((void**)&p_add, g_add);

    const size_t sBCL = (size_t)C_ * L_;     // per-batch stride of [B,C,L]
    const size_t sBLL = (size_t)L_ * L_;     // per-batch stride of [B,L,L]

    // 1. temb MLP + add vector
    temb_kernel<<<B_, 512>>>(t, z0, zt, tw1, tb1, tw2, tb2, tpw, tpb, zpw, zpb);

    // 2. t1 = silu(chan_norm(x, n1))
    norm_kernel<<<B_ * C_, 256>>>(x, p_t1, n1g, n1b, 1);

    // 3. h = conv1(t1) + add
    dim3 gc(L_ / CONV_LT, C_ / CONV_OT, B_);
    conv3_kernel<<<gc, 256>>>(p_t1, c1w, c1b, p_add, nullptr, p_h);

    // 4. t1 = silu(chan_norm(h, n2))
    norm_kernel<<<B_ * C_, 256>>>(p_h, p_t1, n2g, n2b, 1);

    // 5. x1 = x + conv2(t1)
    conv3_kernel<<<gc, 256>>>(p_t1, c2w, c2b, nullptr, x, p_x1);

    // 6. hn = chan_norm(x1, n)   (no silu)
    norm_kernel<<<B_ * C_, 256>>>(p_x1, p_hn, ng, nb, 0);

    // 7. q/k/v = W @ hn + b   (M=C=256, N=L, K=C)
    dim3 gq(L_ / 128, C_ / 128, B_);
    gemm128<1, 0, true, false><<<gq, 256>>>(qw, p_hn, qb, nullptr, p_q,
                                            C_, L_, C_, C_, L_, 1.f, 0, sBCL, sBCL);
    gemm128<1, 0, true, false><<<gq, 256>>>(kw, p_hn, kb, nullptr, p_k,
                                            C_, L_, C_, C_, L_, 1.f, 0, sBCL, sBCL);
    gemm128<1, 0, true, false><<<gq, 256>>>(vw, p_hn, vb, nullptr, p_v,
                                            C_, L_, C_, C_, L_, 1.f, 0, sBCL, sBCL);

    // 8. w[b,i,j] = (1/16) * sum_c q[b,c,i] k[b,c,j]   (M=N=L, K=C)
    dim3 gs(L_ / 128, L_ / 128, B_);
    gemm128<0, 0, false, false><<<gs, 256>>>(p_q, p_k, nullptr, nullptr, p_w,
                                             L_, L_, C_, L_, L_, 0.0625f,
                                             sBCL, sBCL, sBLL);

    // 9. softmax over j
    softmax_kernel<<<B_ * L_, 256>>>(p_w);

    // 10. h2[b,c,i] = sum_j v[b,c,j] w[b,i,j]   (M=C, N=L, K=L)
    dim3 gpv(L_ / 128, C_ / 128, B_);
    gemm128<1, 1, false, false><<<gpv, 256>>>(p_v, p_w, nullptr, nullptr, p_h2,
                                              C_, L_, L_, L_, L_, 1.f,
                                              sBCL, sBLL, sBCL);

    // 11. out = x1 + pw @ h2 + pb
    gemm128<1, 0, true, true><<<gq, 256>>>(pw, p_h2, pb, p_x1, out,
                                           C_, L_, C_, C_, L_, 1.f, 0, sBCL, sBCL);
}

// round 4
// speedup vs baseline: 2.4068x; 2.4068x over previous
#include <cuda_runtime.h>
#include <math.h>
#include <stdint.h>

typedef unsigned int u32;

// ---------------------------------------------------------------------------
// Problem constants
// ---------------------------------------------------------------------------
constexpr int B_    = 16;
constexpr int C_    = 256;
constexpr int L_    = 2048;
constexpr int ZD_   = 128;
constexpr int TEMB_ = 512;
constexpr size_t BCL = (size_t)B_ * C_ * L_;
constexpr size_t BLL = (size_t)B_ * L_ * L_;

// ---------------------------------------------------------------------------
// Scratch (device globals; allocation-free per harness rules)
// ---------------------------------------------------------------------------
__device__ float g_t1 [BCL];                 // silu(norm(.)) staging
__device__ float g_h  [BCL];                 // conv1 output
__device__ float g_x1 [BCL];                 // x + conv2(...)
__device__ float g_hn [BCL];                 // chan_norm(x1)
__device__ float g_hnT[BCL];                 // hn transposed [B][L][C]
__device__ float g_qT [BCL];                 // q^T [B][L][C]
__device__ float g_kT [BCL];                 // k^T [B][L][C]
__device__ float g_v  [BCL];                 // v   [B][C][L]
__device__ float g_h2T[BCL];                 // attn out transposed [B][L][C]
__device__ float g_sc [BLL];                 // scores / softmax (in-place)
__device__ float g_add[B_ * C_];             // temb/z projection vector

static __device__ __forceinline__ float silu_f(float x) {
    return x / (1.f + expf(-x));
}

static __device__ __forceinline__ u32 f2tf(float x) {
    u32 r;
    asm("cvt.rna.tf32.f32 %0, %1;" : "=r"(r) : "f"(x));
    return r;
}

#define MMA_TF32(d, a, b)                                                     \
    asm volatile("mma.sync.aligned.m16n8k8.row.col.f32.tf32.tf32.f32 "       \
                 "{%0,%1,%2,%3},{%4,%5,%6,%7},{%8,%9},{%0,%1,%2,%3};"         \
                 : "+f"(d[0]), "+f"(d[1]), "+f"(d[2]), "+f"(d[3])             \
                 : "r"(a[0]), "r"(a[1]), "r"(a[2]), "r"(a[3]),                \
                   "r"(b[0]), "r"(b[1]))

// ---------------------------------------------------------------------------
// Kernel: timestep embedding MLP + fused add-vector
// ---------------------------------------------------------------------------
__global__ void temb_kernel(const int* __restrict__ t,
                            const float* __restrict__ z0,
                            const float* __restrict__ zt,
                            const float* __restrict__ tw1, const float* __restrict__ tb1,
                            const float* __restrict__ tw2, const float* __restrict__ tb2,
                            const float* __restrict__ tpw, const float* __restrict__ tpb,
                            const float* __restrict__ zpw, const float* __restrict__ zpb)
{
    __shared__ float se[128];
    __shared__ float s1[512];
    __shared__ float s2[512];
    __shared__ float sz[256];

    int b = blockIdx.x, tid = threadIdx.x;

    if (tid < 64) {
        float f = expf((float)tid * (-logf(10000.f) / 63.f));
        float a = (float)t[b] * f;
        se[tid]      = sinf(a);
        se[64 + tid] = cosf(a);
    }
    if (tid < 128) {
        sz[tid]       = silu_f(z0[b * ZD_ + tid]);
        sz[128 + tid] = silu_f(zt[b * ZD_ + tid]);
    }
    __syncthreads();

    {
        float acc = tb1[tid];
        #pragma unroll 8
        for (int i = 0; i < 128; i++) acc += se[i] * tw1[i * TEMB_ + tid];
        s1[tid] = silu_f(acc);
    }
    __syncthreads();
    {
        float acc = tb2[tid];
        #pragma unroll 8
        for (int k = 0; k < 512; k++) acc += s1[k] * tw2[k * TEMB_ + tid];
        s2[tid] = silu_f(acc);
    }
    __syncthreads();

    if (tid < C_) {
        float acc = tpb[tid] + 2.f * zpb[tid];
        #pragma unroll 8
        for (int j = 0; j < 512; j++) acc += s2[j] * tpw[j * C_ + tid];
        #pragma unroll 8
        for (int i = 0; i < 128; i++) acc += (sz[i] + sz[128 + i]) * zpw[i * C_ + tid];
        g_add[b * C_ + tid] = acc;
    }
}

// ---------------------------------------------------------------------------
// Kernel: per-(b,c) channel norm over L, optional fused silu. fp32 -> fp32.
// ---------------------------------------------------------------------------
template <bool DOSILU>
__global__ __launch_bounds__(256) void norm_kernel(const float* __restrict__ in,
                                                   float* __restrict__ out,
                                                   const float* __restrict__ gam,
                                                   const float* __restrict__ bet)
{
    __shared__ float red[64];
    int row = blockIdx.x, tid = threadIdx.x;
    const float* p = in + (size_t)row * L_;

    float v[8];
    float s = 0.f, sq = 0.f;
    #pragma unroll
    for (int i = 0; i < 8; i++) {
        v[i] = p[tid + i * 256];
        s  += v[i];
        sq += v[i] * v[i];
    }
    #pragma unroll
    for (int o = 16; o > 0; o >>= 1) {
        s  += __shfl_down_sync(0xffffffffu, s,  o);
        sq += __shfl_down_sync(0xffffffffu, sq, o);
    }
    if ((tid & 31) == 0) { red[tid >> 5] = s; red[8 + (tid >> 5)] = sq; }
    __syncthreads();
    if (tid < 32) {
        float a  = (tid < 8) ? red[tid]     : 0.f;
        float b2 = (tid < 8) ? red[8 + tid] : 0.f;
        #pragma unroll
        for (int o = 4; o > 0; o >>= 1) {
            a  += __shfl_down_sync(0xffffffffu, a,  o);
            b2 += __shfl_down_sync(0xffffffffu, b2, o);
        }
        if (tid == 0) { red[32] = a; red[33] = b2; }
    }
    __syncthreads();

    float mean = red[32] * (1.f / L_);
    float var  = red[33] * (1.f / L_) - mean * mean;
    float rstd = rsqrtf(var + 1e-6f);
    int c = row & (C_ - 1);
    float gm = gam[c], bt = bet[c];

    float* q = out + (size_t)row * L_;
    #pragma unroll
    for (int i = 0; i < 8; i++) {
        float y = (v[i] - mean) * rstd * gm + bt;
        if (DOSILU) y = y / (1.f + expf(-y));
        q[tid + i * 256] = y;
    }
}

// ---------------------------------------------------------------------------
// Kernel: 32x32 tiled transpose, fp32 [B][C][L] -> fp32 [B][L][C]
// ---------------------------------------------------------------------------
__global__ __launch_bounds__(256) void transpose_f32(const float* __restrict__ in,
                                                     float* __restrict__ out)
{
    __shared__ float tile[32][33];
    int b = blockIdx.z;
    int l0 = blockIdx.x * 32, c0 = blockIdx.y * 32;
    int tx = threadIdx.x & 31, ty = threadIdx.x >> 5;
    #pragma unroll
    for (int i = 0; i < 4; i++) {
        int c = c0 + ty + i * 8;
        tile[ty + i * 8][tx] = in[((size_t)(b * C_ + c)) * L_ + l0 + tx];
    }
    __syncthreads();
    #pragma unroll
    for (int i = 0; i < 4; i++) {
        int l = l0 + ty + i * 8;
        out[((size_t)b * L_ + l) * C_ + c0 + tx] = tile[tx][ty + i * 8];
    }
}

// ---------------------------------------------------------------------------
// tf32 tensor-core GEMM (mma.sync m16n8k8), canonical NT form:
//   C[m][n] = alpha * sum_k A[m][k] * B[n][k]   (lda = ldb = K, ldc = N)
// CTA tile 128x128, k-tile 32. 8 warps: 4(m) x 2(n), warp tile 32x64.
// BIAS_MODE: 0 none, 1 per-m, 2 per-n.  RES: add fp32 residual.
// ---------------------------------------------------------------------------
template <int BIAS_MODE, bool RES>
__global__ __launch_bounds__(256) void gemm_tf32(
    const float* __restrict__ A, const float* __restrict__ Bm,
    const float* __restrict__ bias, const float* __restrict__ res,
    float* __restrict__ Cout, int M, int N, int K, float alpha,
    size_t strideA, size_t strideB, size_t strideC)
{
    __shared__ u32 sA[128][36];   // stride 36: bank(r,c) = 4r+c -> conflict-free frags
    __shared__ u32 sB[128][36];

    int bz = blockIdx.z;
    A  += strideA * bz;
    Bm += strideB * bz;

    int m0 = blockIdx.y * 128, n0 = blockIdx.x * 128;
    int tid = threadIdx.x, lane = tid & 31, w = tid >> 5;
    int wm = (w & 3) * 32, wn = (w >> 2) * 64;
    int g = lane >> 2, tg = lane & 3;

    float acc[2][8][4] = {};

    for (int k0 = 0; k0 < K; k0 += 32) {
        __syncthreads();
        #pragma unroll
        for (int it = 0; it < 4; it++) {
            int idx = tid + it * 256;
            int row = idx >> 3, seg = idx & 7;
            float4 a4 = *(const float4*)&A[(size_t)(m0 + row) * K + k0 + seg * 4];
            float4 b4 = *(const float4*)&Bm[(size_t)(n0 + row) * K + k0 + seg * 4];
            uint4 ta = make_uint4(f2tf(a4.x), f2tf(a4.y), f2tf(a4.z), f2tf(a4.w));
            uint4 tb = make_uint4(f2tf(b4.x), f2tf(b4.y), f2tf(b4.z), f2tf(b4.w));
            *(uint4*)&sA[row][seg * 4] = ta;
            *(uint4*)&sB[row][seg * 4] = tb;
        }
        __syncthreads();

        #pragma unroll
        for (int ks = 0; ks < 4; ks++) {
            int kb = ks * 8 + tg;
            u32 afr[2][4], bfr[8][2];
            #pragma unroll
            for (int mt = 0; mt < 2; mt++) {
                int r = wm + mt * 16 + g;
                afr[mt][0] = sA[r][kb];
                afr[mt][1] = sA[r + 8][kb];
                afr[mt][2] = sA[r][kb + 4];
                afr[mt][3] = sA[r + 8][kb + 4];
            }
            #pragma unroll
            for (int nt = 0; nt < 8; nt++) {
                int c = wn + nt * 8 + g;
                bfr[nt][0] = sB[c][kb];
                bfr[nt][1] = sB[c][kb + 4];
            }
            #pragma unroll
            for (int mt = 0; mt < 2; mt++)
                #pragma unroll
                for (int nt = 0; nt < 8; nt++)
                    MMA_TF32(acc[mt][nt], afr[mt], bfr[nt]);
        }
    }

    // epilogue
    #pragma unroll
    for (int mt = 0; mt < 2; mt++) {
        #pragma unroll
        for (int half = 0; half < 2; half++) {
            int m = m0 + wm + mt * 16 + g + half * 8;
            float bm = (BIAS_MODE == 1) ? bias[m] : 0.f;
            #pragma unroll
            for (int nt = 0; nt < 8; nt++) {
                int n = n0 + wn + nt * 8 + tg * 2;
                float v0 = acc[mt][nt][half * 2 + 0] * alpha;
                float v1 = acc[mt][nt][half * 2 + 1] * alpha;
                if (BIAS_MODE == 1) { v0 += bm; v1 += bm; }
                if (BIAS_MODE == 2) { v0 += bias[n]; v1 += bias[n + 1]; }
                size_t off = strideC * bz + (size_t)m * N + n;
                if (RES) {
                    float2 r2 = *(const float2*)&res[off];
                    v0 += r2.x; v1 += r2.y;
                }
                *(float2*)&Cout[off] = make_float2(v0, v1);
            }
        }
    }
}

// ---------------------------------------------------------------------------
// tf32 tensor-core 3-tap conv (implicit GEMM). pad=1.
//   out[b,o,l] = sum_{ci,t} w[o][ci*3+t] * in[b,ci,l+t-1] + bias[o]
//                (+ addv[b,o]) (+ resid[b,o,l])
// M=C (co), N=L, K=768. CTA tile 128x128, k-tile 48 (16 ci x 3 taps).
// Dynamic smem: 2 * 128*52 u32 = 53248 B.
// ---------------------------------------------------------------------------
constexpr int CONV_SMEM = 2 * 128 * 52 * 4;

template <bool ADDV, bool RES>
__global__ __launch_bounds__(256) void conv_tf32(
    const float* __restrict__ in,   // [B][C][L]
    const float* __restrict__ w,    // [C][C][3] viewed as [C][768]
    const float* __restrict__ bias,
    const float* __restrict__ addv,
    const float* __restrict__ resid,
    float* __restrict__ out)
{
    extern __shared__ u32 smemBuf[];
    u32 (*sA)[52] = (u32(*)[52])smemBuf;               // weights [co][48]
    u32 (*sB)[52] = (u32(*)[52])(smemBuf + 128 * 52);  // patch   [l][48]

    int b  = blockIdx.z;
    int m0 = blockIdx.y * 128;   // output channel
    int l0 = blockIdx.x * 128;   // sequence pos
    int tid = threadIdx.x, lane = tid & 31, wid = tid >> 5;
    int wm = (wid & 3) * 32, wn = (wid >> 2) * 64;
    int g = lane >> 2, tg = lane & 3;

    float acc[2][8][4] = {};

    for (int kt = 0; kt < 16; kt++) {
        int k0 = kt * 48, ci0 = kt * 16;
        __syncthreads();
        // A: weight tile, 128 rows x 48 cols (12 float4 segs per row)
        #pragma unroll
        for (int it = 0; it < 6; it++) {
            int idx = tid + it * 256;
            int row = idx / 12, seg = idx % 12;
            float4 a4 = *(const float4*)&w[(size_t)(m0 + row) * 768 + k0 + seg * 4];
            uint4 ta = make_uint4(f2tf(a4.x), f2tf(a4.y), f2tf(a4.z), f2tf(a4.w));
            *(uint4*)&sA[row][seg * 4] = ta;
        }
        // B: build [l][3*ci+t] patch from input with halo
        for (int idx = tid; idx < 16 * 132; idx += 256) {
            int c = idx / 132, p = idx % 132;
            if (p < 130) {
                int l = l0 - 1 + p;
                float v = 0.f;
                if (l >= 0 && l < L_)
                    v = in[((size_t)(b * C_ + ci0 + c)) * L_ + l];
                u32 tv = f2tf(v);
                #pragma unroll
                for (int t = 0; t < 3; t++) {
                    int j = p - t;
                    if (j >= 0 && j < 128) sB[j][3 * c + t] = tv;
                }
            }
        }
        __syncthreads();

        #pragma unroll
        for (int ks = 0; ks < 6; ks++) {
            int kb = ks * 8 + tg;
            u32 afr[2][4], bfr[8][2];
            #pragma unroll
            for (int mt = 0; mt < 2; mt++) {
                int r = wm + mt * 16 + g;
                afr[mt][0] = sA[r][kb];
                afr[mt][1] = sA[r + 8][kb];
                afr[mt][2] = sA[r][kb + 4];
                afr[mt][3] = sA[r + 8][kb + 4];
            }
            #pragma unroll
            for (int nt = 0; nt < 8; nt++) {
                int c = wn + nt * 8 + g;
                bfr[nt][0] = sB[c][kb];
                bfr[nt][1] = sB[c][kb + 4];
            }
            #pragma unroll
            for (int mt = 0; mt < 2; mt++)
                #pragma unroll
                for (int nt = 0; nt < 8; nt++)
                    MMA_TF32(acc[mt][nt], afr[mt], bfr[nt]);
        }
    }

    #pragma unroll
    for (int mt = 0; mt < 2; mt++) {
        #pragma unroll
        for (int half = 0; half < 2; half++) {
            int m = m0 + wm + mt * 16 + g + half * 8;
            float base = bias[m];
            if (ADDV) base += addv[b * C_ + m];
            #pragma unroll
            for (int nt = 0; nt < 8; nt++) {
                int n = l0 + wn + nt * 8 + tg * 2;
                float v0 = acc[mt][nt][half * 2 + 0] + base;
                float v1 = acc[mt][nt][half * 2 + 1] + base;
                size_t off = ((size_t)(b * C_ + m)) * L_ + n;
                if (RES) {
                    float2 r2 = *(const float2*)&resid[off];
                    v0 += r2.x; v1 += r2.y;
                }
                *(float2*)&out[off] = make_float2(v0, v1);
            }
        }
    }
}

// ---------------------------------------------------------------------------
// Row softmax in-place (fp32). One block (256 thr) per (b,i) row.
// ---------------------------------------------------------------------------
__global__ __launch_bounds__(256) void softmax_kernel(float* __restrict__ w)
{
    __shared__ float red[8];
    __shared__ float red2[8];
    size_t row = blockIdx.x;
    float* p = w + row * (size_t)L_;
    int tid = threadIdx.x;

    float v[8];
    float mx = -1e30f;
    #pragma unroll
    for (int i = 0; i < 8; i++) { v[i] = p[tid + i * 256]; mx = fmaxf(mx, v[i]); }
    #pragma unroll
    for (int o = 16; o > 0; o >>= 1) mx = fmaxf(mx, __shfl_xor_sync(0xffffffffu, mx, o));
    if ((tid & 31) == 0) red[tid >> 5] = mx;
    __syncthreads();
    float m = red[0];
    #pragma unroll
    for (int i = 1; i < 8; i++) m = fmaxf(m, red[i]);

    float s = 0.f;
    #pragma unroll
    for (int i = 0; i < 8; i++) { v[i] = expf(v[i] - m); s += v[i]; }
    #pragma unroll
    for (int o = 16; o > 0; o >>= 1) s += __shfl_xor_sync(0xffffffffu, s, o);
    if ((tid & 31) == 0) red2[tid >> 5] = s;
    __syncthreads();
    float tot = 0.f;
    #pragma unroll
    for (int i = 0; i < 8; i++) tot += red2[i];
    float inv = 1.f / tot;
    #pragma unroll
    for (int i = 0; i < 8; i++) p[tid + i * 256] = v[i] * inv;
}

// ---------------------------------------------------------------------------
// Host orchestration (graph-capturable: kernel launches only)
// ---------------------------------------------------------------------------
extern "C" void kernel_launch(void* const* d_in, const int* in_sizes, int n_in,
                              void* d_out, int out_size)
{
    (void)in_sizes; (void)n_in; (void)out_size;

    const float* x   = (const float*)d_in[0];
    const int*   t   = (const int*)  d_in[1];
    const float* z0  = (const float*)d_in[2];
    const float* zt  = (const float*)d_in[3];
    const float* tw1 = (const float*)d_in[4];
    const float* tb1 = (const float*)d_in[5];
    const float* tw2 = (const float*)d_in[6];
    const float* tb2 = (const float*)d_in[7];
    const float* tpw = (const float*)d_in[8];
    const float* tpb = (const float*)d_in[9];
    const float* zpw = (const float*)d_in[10];
    const float* zpb = (const float*)d_in[11];
    const float* n1g = (const float*)d_in[12];
    const float* n1b = (const float*)d_in[13];
    const float* n2g = (const float*)d_in[14];
    const float* n2b = (const float*)d_in[15];
    const float* ng  = (const float*)d_in[16];
    const float* nb  = (const float*)d_in[17];
    const float* c1w = (const float*)d_in[18];
    const float* c1b = (const float*)d_in[19];
    const float* c2w = (const float*)d_in[20];
    const float* c2b = (const float*)d_in[21];
    const float* qw  = (const float*)d_in[22];
    const float* qb  = (const float*)d_in[23];
    const float* kw  = (const float*)d_in[24];
    const float* kb  = (const float*)d_in[25];
    const float* vw  = (const float*)d_in[26];
    const float* vb  = (const float*)d_in[27];
    const float* pw  = (const float*)d_in[28];
    const float* pb  = (const float*)d_in[29];
    float* out = (float*)d_out;

    float *p_t1, *p_h, *p_x1, *p_hn, *p_hnT, *p_qT, *p_kT, *p_v, *p_h2T, *p_sc, *p_add;
    cudaGetSymbolAddress((void**)&p_t1,  g_t1);
    cudaGetSymbolAddress((void**)&p_h,   g_h);
    cudaGetSymbolAddress((void**)&p_x1,  g_x1);
    cudaGetSymbolAddress((void**)&p_hn,  g_hn);
    cudaGetSymbolAddress((void**)&p_hnT, g_hnT);
    cudaGetSymbolAddress((void**)&p_qT,  g_qT);
    cudaGetSymbolAddress((void**)&p_kT,  g_kT);
    cudaGetSymbolAddress((void**)&p_v,   g_v);
    cudaGetSymbolAddress((void**)&p_h2T, g_h2T);
    cudaGetSymbolAddress((void**)&p_sc,  g_sc);
    cudaGetSymbolAddress((void**)&p_add, g_add);

    // allow 53KB dynamic smem for the conv kernels (idempotent, host-side)
    cudaFuncSetAttribute(conv_tf32<true, false>,
                         cudaFuncAttributeMaxDynamicSharedMemorySize, CONV_SMEM);
    cudaFuncSetAttribute(conv_tf32<false, true>,
                         cudaFuncAttributeMaxDynamicSharedMemorySize, CONV_SMEM);

    const size_t sCL = (size_t)C_ * L_;   // per-batch stride, [B,C,L] / [B,L,C]
    const size_t sLL = (size_t)L_ * L_;   // per-batch stride, [B,L,L]

    // 1. temb MLP + add vector
    temb_kernel<<<B_, 512>>>(t, z0, zt, tw1, tb1, tw2, tb2, tpw, tpb, zpw, zpb);

    // 2. t1 = silu(chan_norm(x, n1))
    norm_kernel<true><<<B_ * C_, 256>>>(x, p_t1, n1g, n1b);

    // 3. h = conv1(t1) + add
    dim3 gconv(L_ / 128, C_ / 128, B_);
    conv_tf32<true, false><<<gconv, 256, CONV_SMEM>>>(p_t1, c1w, c1b, p_add, nullptr, p_h);

    // 4. t1 = silu(chan_norm(h, n2))
    norm_kernel<true><<<B_ * C_, 256>>>(p_h, p_t1, n2g, n2b);

    // 5. x1 = x + conv2(t1)
    conv_tf32<false, true><<<gconv, 256, CONV_SMEM>>>(p_t1, c2w, c2b, nullptr, x, p_x1);

    // 6. hn = chan_norm(x1, n), then transpose -> hnT [B][L][C]
    norm_kernel<false><<<B_ * C_, 256>>>(p_x1, p_hn, ng, nb);
    dim3 gtr(L_ / 32, C_ / 32, B_);
    transpose_f32<<<gtr, 256>>>(p_hn, p_hnT);

    // 7. qT/kT [L][C] = hnT @ w^T + b(per-n)     M=L, N=C, K=C
    dim3 gqk(C_ / 128, L_ / 128, B_);
    gemm_tf32<2, false><<<gqk, 256>>>(p_hnT, qw, qb, nullptr, p_qT,
                                      L_, C_, C_, 1.f, sCL, 0, sCL);
    gemm_tf32<2, false><<<gqk, 256>>>(p_hnT, kw, kb, nullptr, p_kT,
                                      L_, C_, C_, 1.f, sCL, 0, sCL);
    //    v [C][L] = w @ hn + b(per-m)            M=C, N=L, K=C
    dim3 gv(L_ / 128, C_ / 128, B_);
    gemm_tf32<1, false><<<gv, 256>>>(vw, p_hnT, vb, nullptr, p_v,
                                     C_, L_, C_, 1.f, 0, sCL, sCL);

    // 8. scores[i][j] = (1/16) qT[i]·kT[j]       M=N=L, K=C
    dim3 gsc(L_ / 128, L_ / 128, B_);
    gemm_tf32<0, false><<<gsc, 256>>>(p_qT, p_kT, nullptr, nullptr, p_sc,
                                      L_, L_, C_, 0.0625f, sCL, sCL, sLL);

    // 9. softmax over j (in place)
    softmax_kernel<<<B_ * L_, 256>>>(p_sc);

    // 10. h2T[i][c] = sum_j sc[i][j] v[c][j]     M=L, N=C, K=L
    dim3 gh2(C_ / 128, L_ / 128, B_);
    gemm_tf32<0, false><<<gh2, 256>>>(p_sc, p_v, nullptr, nullptr, p_h2T,
                                      L_, C_, L_, 1.f, sLL, sCL, sCL);

    // 11. out[c][l] = pw @ h2 + pb + x1          M=C, N=L, K=C
    dim3 gpr(L_ / 128, C_ / 128, B_);
    gemm_tf32<1, true><<<gpr, 256>>>(pw, p_h2T, pb, p_x1, out,
                                     C_, L_, C_, 1.f, 0, sCL, sCL);
}